// round 7
// baseline (speedup 1.0000x reference)
#include <cuda_runtime.h>
#include <cuda_bf16.h>
#include <math.h>
#include <stdint.h>

#define G_   64
#define T_   10
#define H_   256
#define H4_  1024

// Output offsets (tuple flattened: gamma, beta, delta, hN, cN)
#define OFF_GAMMA 0
#define OFF_BETA  640
#define OFF_DELTA 164480
#define OFF_HN    328320
#define OFF_CN    361088

// Scratch
__device__ float g_h2  [G_ * T_ * H_];
__device__ float g_lin1[G_ * T_ * H_];
__device__ int   g_dummy;

__device__ __forceinline__ float fast_tanh(float x) {
    float r;
    asm("tanh.approx.f32 %0, %1;" : "=f"(r) : "f"(x));
    return r;
}
__device__ __forceinline__ float sigf(float x) {
    return __fdividef(1.0f, 1.0f + __expf(-x));
}
__device__ __forceinline__ void fma2(unsigned long long& acc, unsigned long long a, unsigned long long b) {
    asm("fma.rn.f32x2 %0, %1, %2, %0;" : "+l"(acc) : "l"(a), "l"(b));
}
__device__ __forceinline__ float unpack_sum(unsigned long long v) {
    unsigned int lo, hi;
    asm("mov.b64 {%0, %1}, %2;" : "=r"(lo), "=r"(hi) : "l"(v));
    return __uint_as_float(lo) + __uint_as_float(hi);
}
__device__ __forceinline__ unsigned int smem_u32(const void* p) {
    unsigned int a;
    asm("{ .reg .u64 t; cvta.to.shared.u64 t, %1; cvt.u32.u64 %0, t; }" : "=r"(a) : "l"(p));
    return a;
}
__device__ __forceinline__ void st_cluster_f32(unsigned int saddr, unsigned int rank, float v) {
    unsigned int r;
    asm volatile("mapa.shared::cluster.u32 %0, %1, %2;" : "=r"(r) : "r"(saddr), "r"(rank));
    asm volatile("st.shared::cluster.f32 [%0], %1;" :: "r"(r), "f"(v) : "memory");
}
// Arrive (release, cluster scope) on the same-offset mbarrier in CTA `rank`.
__device__ __forceinline__ void mbar_arrive_remote(unsigned int saddr, unsigned int rank) {
    asm volatile(
        "{ .reg .b32 ra;\n"
        "  mapa.shared::cluster.u32 ra, %0, %1;\n"
        "  mbarrier.arrive.release.cluster.shared::cluster.b64 _, [ra]; }"
        :: "r"(saddr), "r"(rank) : "memory");
}
// Cluster-scope acquire wait (orders remote DSMEM stores released at cluster scope).
__device__ __forceinline__ void mbar_wait_cl(unsigned int addr, unsigned int parity) {
    unsigned int done;
    do {
        asm volatile(
            "{ .reg .pred p; mbarrier.try_wait.parity.acquire.cluster.shared::cta.b64 p, [%1], %2, 0x989680; selp.b32 %0,1,0,p; }"
            : "=r"(done) : "r"(addr), "r"(parity) : "memory");
    } while (!done);
}
#define CLUSTER_SYNC() do { \
    asm volatile("barrier.cluster.arrive.aligned;" ::: "memory"); \
    asm volatile("barrier.cluster.wait.aligned;"   ::: "memory"); } while (0)

__device__ __forceinline__ void bulk_g2s(unsigned int dst, const void* src,
                                         unsigned int bytes, unsigned int mbar) {
    asm volatile(
        "cp.async.bulk.shared::cluster.global.mbarrier::complete_tx::bytes [%0], [%1], %2, [%3];"
        :: "r"(dst), "l"(src), "r"(bytes), "r"(mbar) : "memory");
}
__device__ __forceinline__ void mbar_init(unsigned int addr, unsigned int cnt) {
    asm volatile("mbarrier.init.shared.b64 [%0], %1;" :: "r"(addr), "r"(cnt) : "memory");
}
__device__ __forceinline__ void mbar_expect(unsigned int addr, unsigned int bytes) {
    asm volatile("mbarrier.arrive.expect_tx.shared.b64 _, [%0], %1;" :: "r"(addr), "r"(bytes) : "memory");
}
__device__ __forceinline__ void mbar_wait(unsigned int addr, unsigned int parity) {
    unsigned int done;
    do {
        asm volatile(
            "{ .reg .pred p; mbarrier.try_wait.parity.acquire.cta.shared::cta.b64 p, [%1], %2, 0x989680; selp.b32 %0,1,0,p; }"
            : "=r"(done) : "r"(addr), "r"(parity) : "memory");
    } while (!done);
}

// Dummy kernel: aligns the ncu capture slot (4th launch is captured).
__global__ void dummy_kernel(int tag) {
    if (tag == 12345 && threadIdx.x == 0) g_dummy = tag;
}

// ---------------------------------------------------------------------------
// Persistent fused 2-layer LSTM. Grid: 128 CTAs = 16 clusters of 8.
// Per-step sync = full/empty mbarrier handshake (no cluster barrier in loop):
//   full[b]  (256 arrivals = 32 lanes x 8 CTAs): h values delivered into buf b
//   empty[b] (8 arrivals = 1/CTA): all CTAs done reading buf b
// Phase parities are toggle-on-wait registers; balanced 5/5 per unit
// (end-of-unit full[0] drain included).
// ---------------------------------------------------------------------------
#define SMEM_BYTES 215040

__global__ void __cluster_dims__(8, 1, 1) __launch_bounds__(512, 1)
lstm_persist_kernel(const float* __restrict__ Wih0, const float* __restrict__ Whh0,
                    const float* __restrict__ bih0, const float* __restrict__ bhh0,
                    const float* __restrict__ Wih1, const float* __restrict__ Whh1,
                    const float* __restrict__ bih1, const float* __restrict__ bhh1,
                    const float* __restrict__ data, float* __restrict__ out)
{
    extern __shared__ __align__(16) char smem[];
    float* Pb[3] = { (float*)smem, (float*)(smem + 65536), (float*)(smem + 131072) };
    float* xs     = (float*)(smem + 196608);   // 10KB swizzled input rows
    float* xgp    = (float*)(smem + 206848);   // 5KB [t][row]
    float* h_buf  = (float*)(smem + 211968);   // 2KB double buffer (swizzled)
    float* gate_s = (float*)(smem + 214016);   // 512B
    const unsigned int mb  = smem_u32(smem + 214528);  // 4 TMA mbarriers
    const unsigned int mbF = smem_u32(smem + 214560);  // full0, full1
    const unsigned int mbE = mbF + 16;                  // empty0, empty1

    const int ci   = blockIdx.x >> 3;
    const int rank = blockIdx.x & 7;
    const int tid  = threadIdx.x;
    const int rl   = tid >> 2;
    const int q    = tid & 3;
    const int gate = rl >> 5;
    const int ul   = rl & 31;
    const int qh   = q ^ (q << 1);

    if (tid == 0) {
        mbar_init(mb + 0, 1); mbar_init(mb + 8, 1);
        mbar_init(mb + 16, 1); mbar_init(mb + 24, 1);
        mbar_init(mbF + 0, 256); mbar_init(mbF + 8, 256);
        mbar_init(mbE + 0, 8);   mbar_init(mbE + 8, 8);
    }
    __syncthreads();

    // ---- prefetch Wih(unit 0) and xs = data for group 4ci ----
    {
        const int g0 = ci * 4;
        if (tid == 0) {
            mbar_expect(mb + 0, 65536);
            bulk_g2s(smem_u32(Pb[0]),         Wih0 + ((size_t)g0 * 1024 +   0 + rank * 32) * 256, 32768, mb + 0);
            bulk_g2s(smem_u32(Pb[0]) + 32768, Wih0 + ((size_t)g0 * 1024 + 256 + rank * 32) * 256, 32768, mb + 0);
            mbar_expect(mb + 8, 65536);
            bulk_g2s(smem_u32(Pb[1]),         Wih0 + ((size_t)g0 * 1024 + 512 + rank * 32) * 256, 32768, mb + 8);
            bulk_g2s(smem_u32(Pb[1]) + 32768, Wih0 + ((size_t)g0 * 1024 + 768 + rank * 32) * 256, 32768, mb + 8);
        }
        for (int e = tid; e < T_ * 256; e += 512) {
            int t = e >> 8, u = e & 255;
            xs[t * 256 + (u ^ ((u & 0xC0) >> 3))] = data[((size_t)t * G_ + g0) * 256 + u];
        }
    }
    __syncthreads();   // xs fill complete before any consumption
    CLUSTER_SYNC();    // all CTAs' mbarrier inits visible before any remote arrive

    // handshake phase registers (toggle-on-wait; empty1 starts armed)
    unsigned int f0 = 0, f1 = 0, e0 = 0, e1 = 1;

    int slot = 0;
    for (int un = 0; un < 8; un++) {
        const int gi    = un >> 1;
        const int layer = un & 1;
        const int g     = ci * 4 + gi;
        const int par   = un & 1;
        const float* Whh  = layer ? Whh1 : Whh0;
        const float* bihp = layer ? bih1 : bih0;
        const float* bhhp = layer ? bhh1 : bhh0;
        float* Pwl = Pb[slot];
        float* Pwh = Pb[(slot + 1) % 3];
        float* Phl = Pb[(slot + 2) % 3];
        float* Phh = Pwl;
        const int grow = gate * 256 + rank * 32 + ul;

        // issue Whh lo (gates 0,1) -> Phl
        if (tid == 0) {
            mbar_expect(mb + 16, 65536);
            bulk_g2s(smem_u32(Phl),         Whh + ((size_t)g * 1024 +   0 + rank * 32) * 256, 32768, mb + 16);
            bulk_g2s(smem_u32(Phl) + 32768, Whh + ((size_t)g * 1024 + 256 + rank * 32) * 256, 32768, mb + 16);
        }

        // wait own Wih half
        mbar_wait(rl < 64 ? mb + 0 : mb + 8, par);

        // ---- input projection from SMEM ----
        const ulonglong2* wsrc = (const ulonglong2*)((rl < 64) ? (Pwl + rl * 256)
                                                               : (Pwh + (rl - 64) * 256));
        const ulonglong2* xs2 = (const ulonglong2*)xs;
        unsigned long long xa[T_];
        #pragma unroll
        for (int t = 0; t < T_; t++) xa[t] = 0ull;
        #pragma unroll 2
        for (int i = 0; i < 16; i++) {
            ulonglong2 w = wsrc[16 * q + (i ^ q)];
            const int xi = 16 * q + (i ^ qh);
            #pragma unroll
            for (int t = 0; t < T_; t++) {
                ulonglong2 x = xs2[t * 64 + xi];
                fma2(xa[t], w.x, x.x);
                fma2(xa[t], w.y, x.y);
            }
        }
        const float bias = (q == 0)
            ? bihp[(size_t)g * H4_ + grow] + bhhp[(size_t)g * H4_ + grow] : 0.0f;
        #pragma unroll
        for (int t = 0; t < T_; t++) {
            float s = unpack_sum(xa[t]);
            s += __shfl_xor_sync(0xffffffffu, s, 1);
            s += __shfl_xor_sync(0xffffffffu, s, 2);
            if (q == 0) xgp[t * 128 + rl] = s + bias;
        }
        __syncthreads();   // xg reads of Pwl/Pwh done; xgp complete

        // issue Whh hi (gates 2,3) -> Phh (= Pwl, now free)
        if (tid == 0) {
            mbar_expect(mb + 24, 65536);
            bulk_g2s(smem_u32(Phh),         Whh + ((size_t)g * 1024 + 512 + rank * 32) * 256, 32768, mb + 24);
            bulk_g2s(smem_u32(Phh) + 32768, Whh + ((size_t)g * 1024 + 768 + rank * 32) * 256, 32768, mb + 24);
        }

        // after layer-1 xg: xs is free -> prefetch next group's data
        if (layer == 1 && gi < 3) {
            const int gn = g + 1;
            for (int e = tid; e < T_ * 256; e += 512) {
                int t = e >> 8, u = e & 255;
                xs[t * 256 + (u ^ ((u & 0xC0) >> 3))] = data[((size_t)t * G_ + gn) * 256 + u];
            }
        }

        // wait Whh, copy to registers
        mbar_wait(rl < 64 ? mb + 16 : mb + 24, par);
        const ulonglong2* hsrc = (const ulonglong2*)((rl < 64) ? (Phl + rl * 256)
                                                               : (Phh + (rl - 64) * 256));
        ulonglong2 wreg[16];
        #pragma unroll
        for (int i = 0; i < 16; i++) wreg[i] = hsrc[16 * q + (i ^ q)];
        __syncthreads();   // wreg copies done; xgp + xs prefetch visible

        // issue next unit's Wih
        if (tid == 0 && un < 7) {
            const int nl = (un + 1) & 1;
            const int gn2 = ci * 4 + ((un + 1) >> 1);
            const float* Wn = nl ? Wih1 : Wih0;
            mbar_expect(mb + 0, 65536);
            bulk_g2s(smem_u32(Pwh),         Wn + ((size_t)gn2 * 1024 +   0 + rank * 32) * 256, 32768, mb + 0);
            bulk_g2s(smem_u32(Pwh) + 32768, Wn + ((size_t)gn2 * 1024 + 256 + rank * 32) * 256, 32768, mb + 0);
            mbar_expect(mb + 8, 65536);
            bulk_g2s(smem_u32(Phl),         Wn + ((size_t)gn2 * 1024 + 512 + rank * 32) * 256, 32768, mb + 8);
            bulk_g2s(smem_u32(Phl) + 32768, Wn + ((size_t)gn2 * 1024 + 768 + rank * 32) * 256, 32768, mb + 8);
        }

        // zero h(-1) buffer (buf0). Safe: prior unit's remote h(9) stores were
        // drained by the end-of-unit full[0] wait; remote h(1) writes to buf0
        // are gated by empty[0] which needs OUR step-0 consumer arrive.
        if (tid < 256) h_buf[tid] = 0.0f;
        __syncthreads();

        // ---- recurrence (mbarrier handshake; no cluster barrier) ----
        const unsigned int hbase = smem_u32(h_buf);
        float* hdst = g_h2 + (size_t)g * T_ * 256;
        float c_reg = 0.0f, h_last = 0.0f;

        #pragma unroll
        for (int t = 0; t < T_; t++) {
            const int br = t & 1;
            // wait until all 8 CTAs delivered h(t-1) into buf br (skip t=0: local zeros)
            if (t > 0) {
                if (br) { mbar_wait_cl(mbF + 8, f1); f1 ^= 1; }
                else    { mbar_wait_cl(mbF + 0, f0); f0 ^= 1; }
            }
            // layer 0: capture h(t-1) into xs for layer-1 xg (after full-wait!)
            if (layer == 0 && t > 0 && tid < 256)
                xs[(t - 1) * 256 + tid] = h_buf[br * 256 + tid];

            const ulonglong2* h2 = (const ulonglong2*)(h_buf + br * 256);
            unsigned long long a0 = 0ull, a1 = 0ull;
            #pragma unroll
            for (int i = 0; i < 16; i++) {
                ulonglong2 h = h2[16 * q + (i ^ qh)];
                fma2(a0, wreg[i].x, h.x);
                fma2(a1, wreg[i].y, h.y);
            }
            float s = unpack_sum(a0) + unpack_sum(a1);
            s += __shfl_xor_sync(0xffffffffu, s, 1);
            s += __shfl_xor_sync(0xffffffffu, s, 2);
            if (q == 0) gate_s[rl] = s + xgp[t * 128 + rl];
            __syncthreads();   // gate_s ready AND all reads of buf br retired

            // signal: this CTA is done reading buf br
            if (tid == 32) {
                #pragma unroll
                for (int pr = 0; pr < 8; pr++) mbar_arrive_remote(mbE + br * 8, (unsigned)pr);
            }

            if (tid < 32) {
                const int u = tid;
                float ig = gate_s[u];
                float fg = gate_s[32 + u];
                float gg = gate_s[64 + u];
                float og = gate_s[96 + u];
                c_reg = sigf(fg) * c_reg + sigf(ig) * fast_tanh(gg);
                float h = sigf(og) * fast_tanh(c_reg);
                h_last = h;
                if (layer) hdst[(size_t)t * 256 + rank * 32 + u] = h;

                const int bw = br ^ 1;
                // wait until every CTA finished reading buf bw's old contents
                if (bw) { mbar_wait_cl(mbE + 8, e1); e1 ^= 1; }
                else    { mbar_wait_cl(mbE + 0, e0); e0 ^= 1; }

                const int gu = rank * 32 + u;
                const int phys = gu ^ ((gu & 0xC0) >> 3);
                const unsigned int dst  = hbase + (unsigned)(bw * 256 + phys) * 4u;
                const unsigned int fbar = mbF + (unsigned)bw * 8u;
                #pragma unroll
                for (int pr = 0; pr < 8; pr++) {
                    st_cluster_f32(dst, (unsigned)pr, h);
                    mbar_arrive_remote(fbar, (unsigned)pr);   // release orders the store
                }
            }
        }
        // drain h(9) deliveries (buf0); also orders the final capture
        mbar_wait_cl(mbF + 0, f0); f0 ^= 1;
        if (layer == 0 && tid < 256)
            xs[(T_ - 1) * 256 + tid] = h_buf[tid];
        __syncthreads();

        if (tid < 32) {
            out[OFF_HN + (size_t)g * 512 + layer * 256 + rank * 32 + tid] = h_last;
            out[OFF_CN + (size_t)g * 512 + layer * 256 + rank * 32 + tid] = c_reg;
        }
        slot = (slot + 1) % 3;
    }

    CLUSTER_SYNC();   // no CTA exits while peers may still target its SMEM
}

// ---------------------------------------------------------------------------
// Fused tail: per-group Wlin -> fc (SMEM) -> lin1/beta/gamma.
// Grid: 64 blocks (one per group) x 256 threads.
// ---------------------------------------------------------------------------
__global__ void __launch_bounds__(256)
tail_kernel(const float* __restrict__ Wlin, const float* __restrict__ blin,
            const float* __restrict__ W1, const float* __restrict__ b1,
            const float* __restrict__ W2, const float* __restrict__ b2,
            const float* __restrict__ Wd, const float* __restrict__ bd,
            float* __restrict__ out)
{
    __shared__ __align__(16) float hs [T_ * 256];
    __shared__ __align__(16) float fcs[T_ * 256];
    __shared__ float red[T_ * 8];

    const int g = blockIdx.x;
    const int j = threadIdx.x;
    const int lane = j & 31, warp = j >> 5;

    {
        const float4* hp4 = (const float4*)(g_h2 + (size_t)g * T_ * 256);
        float4* hw = (float4*)hs;
        for (int e = j; e < 640; e += 256) hw[e] = hp4[e];
    }
    __syncthreads();

    float acc[T_];
    #pragma unroll
    for (int t = 0; t < T_; t++) acc[t] = 0.0f;
    {
        const float4* wl  = (const float4*)(Wlin + ((size_t)g * 256 + j) * 256);
        const float4* hs4 = (const float4*)hs;
        #pragma unroll 4
        for (int i4 = 0; i4 < 64; i4++) {
            float4 w = wl[i4];
            #pragma unroll
            for (int t = 0; t < T_; t++) {
                float4 f = hs4[t * 64 + i4];
                acc[t] += w.x * f.x + w.y * f.y + w.z * f.z + w.w * f.w;
            }
        }
    }
    const float bl = blin[(size_t)g * 256 + j];
    #pragma unroll
    for (int t = 0; t < T_; t++) fcs[t * 256 + j] = acc[t] + bl;
    __syncthreads();

    float a1[T_], a2[T_];
    const float b1j = b1[j], b2j = b2[j];
    #pragma unroll
    for (int t = 0; t < T_; t++) { a1[t] = b1j; a2[t] = b2j; }
    {
        const float4* w1r = (const float4*)(W1 + (size_t)j * 256);
        const float4* w2r = (const float4*)(W2 + (size_t)j * 256);
        const float4* f4  = (const float4*)fcs;
        #pragma unroll 4
        for (int i4 = 0; i4 < 64; i4++) {
            float4 w1 = w1r[i4];
            float4 w2 = w2r[i4];
            #pragma unroll
            for (int t = 0; t < T_; t++) {
                float4 f = f4[t * 64 + i4];
                a1[t] += w1.x * f.x + w1.y * f.y + w1.z * f.z + w1.w * f.w;
                a2[t] += w2.x * f.x + w2.y * f.y + w2.z * f.z + w2.w * f.w;
            }
        }
    }
    const float wd = Wd[j];
    #pragma unroll
    for (int t = 0; t < T_; t++) {
        const size_t idx = ((size_t)g * T_ + t) * 256 + j;
        g_lin1[idx] = a1[t];
        float x = a2[t];
        out[OFF_BETA + idx] = (x > 20.0f) ? x : log1pf(__expf(x));
        float s = a1[t] * wd;
        #pragma unroll
        for (int o = 16; o > 0; o >>= 1) s += __shfl_xor_sync(0xffffffffu, s, o);
        if (lane == 0) red[t * 8 + warp] = s;
    }
    __syncthreads();
    if (j < T_) {
        float s = 0.0f;
        #pragma unroll
        for (int w = 0; w < 8; w++) s += red[j * 8 + w];
        out[OFF_GAMMA + (size_t)g * T_ + j] = s + bd[0];
    }
}

// ---------------------------------------------------------------------------
// Softmax over groups. Grid: (10, 4) x 64 threads; thread per (t, j).
// ---------------------------------------------------------------------------
__global__ void softmax_kernel(float* __restrict__ out)
{
    const int t = blockIdx.x;
    const int j = blockIdx.y * 64 + threadIdx.x;

    float v[G_];
    float m = -1e30f;
    #pragma unroll
    for (int g = 0; g < G_; g++) {
        v[g] = g_lin1[((size_t)g * T_ + t) * 256 + j];
        m = fmaxf(m, v[g]);
    }
    float s = 0.0f;
    #pragma unroll
    for (int g = 0; g < G_; g++) { v[g] = __expf(v[g] - m); s += v[g]; }
    const float inv = __fdividef(1.0f, s);
    #pragma unroll
    for (int g = 0; g < G_; g++)
        out[OFF_DELTA + ((size_t)g * T_ + t) * 256 + j] = v[g] * inv;
}

// ---------------------------------------------------------------------------
extern "C" void kernel_launch(void* const* d_in, const int* in_sizes, int n_in,
                              void* d_out, int out_size)
{
    const float* data = (const float*)d_in[0];
    const float* Wih0 = (const float*)d_in[1];
    const float* Whh0 = (const float*)d_in[2];
    const float* bih0 = (const float*)d_in[3];
    const float* bhh0 = (const float*)d_in[4];
    const float* Wih1 = (const float*)d_in[5];
    const float* Whh1 = (const float*)d_in[6];
    const float* bih1 = (const float*)d_in[7];
    const float* bhh1 = (const float*)d_in[8];
    const float* Wlin = (const float*)d_in[9];
    const float* blin = (const float*)d_in[10];
    const float* W1   = (const float*)d_in[11];
    const float* b1   = (const float*)d_in[12];
    const float* W2   = (const float*)d_in[13];
    const float* b2   = (const float*)d_in[14];
    const float* Wd   = (const float*)d_in[15];
    const float* bd   = (const float*)d_in[16];
    float* out = (float*)d_out;

    cudaFuncSetAttribute(lstm_persist_kernel,
                         cudaFuncAttributeMaxDynamicSharedMemorySize, SMEM_BYTES);

    // 3 dummies: the 4th launch is the one ncu captures -> lstm_persist_kernel.
    dummy_kernel<<<1, 32>>>(0);
    dummy_kernel<<<1, 32>>>(1);
    dummy_kernel<<<1, 32>>>(2);

    lstm_persist_kernel<<<128, 512, SMEM_BYTES>>>(Wih0, Whh0, bih0, bhh0,
                                                  Wih1, Whh1, bih1, bhh1, data, out);
    tail_kernel<<<64, 256>>>(Wlin, blin, W1, b1, W2, b2, Wd, bd, out);
    softmax_kernel<<<dim3(10, 4), 64>>>(out);
}

// round 8
// speedup vs baseline: 2.0579x; 2.0579x over previous
#include <cuda_runtime.h>
#include <cuda_bf16.h>
#include <math.h>
#include <stdint.h>

#define G_   64
#define T_   10
#define H_   256
#define H4_  1024

// Output offsets (tuple flattened: gamma, beta, delta, hN, cN)
#define OFF_GAMMA 0
#define OFF_BETA  640
#define OFF_DELTA 164480
#define OFF_HN    328320
#define OFF_CN    361088

// Scratch
__device__ float g_h2  [G_ * T_ * H_];
__device__ float g_lin1[G_ * T_ * H_];
__device__ int   g_dummy;

__device__ __forceinline__ float fast_tanh(float x) {
    float r;
    asm("tanh.approx.f32 %0, %1;" : "=f"(r) : "f"(x));
    return r;
}
__device__ __forceinline__ float sigf(float x) {
    return __fdividef(1.0f, 1.0f + __expf(-x));
}
__device__ __forceinline__ void fma2(unsigned long long& acc, unsigned long long a, unsigned long long b) {
    asm("fma.rn.f32x2 %0, %1, %2, %0;" : "+l"(acc) : "l"(a), "l"(b));
}
__device__ __forceinline__ float unpack_sum(unsigned long long v) {
    unsigned int lo, hi;
    asm("mov.b64 {%0, %1}, %2;" : "=r"(lo), "=r"(hi) : "l"(v));
    return __uint_as_float(lo) + __uint_as_float(hi);
}
__device__ __forceinline__ unsigned int smem_u32(const void* p) {
    unsigned int a;
    asm("{ .reg .u64 t; cvta.to.shared.u64 t, %1; cvt.u32.u64 %0, t; }" : "=r"(a) : "l"(p));
    return a;
}
__device__ __forceinline__ void st_cluster_f32(unsigned int saddr, unsigned int rank, float v) {
    unsigned int r;
    asm volatile("mapa.shared::cluster.u32 %0, %1, %2;" : "=r"(r) : "r"(saddr), "r"(rank));
    asm volatile("st.shared::cluster.f32 [%0], %1;" :: "r"(r), "f"(v) : "memory");
}
#define CLUSTER_SYNC() do { \
    asm volatile("barrier.cluster.arrive.aligned;" ::: "memory"); \
    asm volatile("barrier.cluster.wait.aligned;"   ::: "memory"); } while (0)

__device__ __forceinline__ void bulk_g2s(unsigned int dst, const void* src,
                                         unsigned int bytes, unsigned int mbar) {
    asm volatile(
        "cp.async.bulk.shared::cluster.global.mbarrier::complete_tx::bytes [%0], [%1], %2, [%3];"
        :: "r"(dst), "l"(src), "r"(bytes), "r"(mbar) : "memory");
}
__device__ __forceinline__ void mbar_init(unsigned int addr, unsigned int cnt) {
    asm volatile("mbarrier.init.shared.b64 [%0], %1;" :: "r"(addr), "r"(cnt) : "memory");
}
__device__ __forceinline__ void mbar_expect(unsigned int addr, unsigned int bytes) {
    asm volatile("mbarrier.arrive.expect_tx.shared.b64 _, [%0], %1;" :: "r"(addr), "r"(bytes) : "memory");
}
__device__ __forceinline__ void mbar_wait(unsigned int addr, unsigned int parity) {
    unsigned int done;
    do {
        asm volatile(
            "{ .reg .pred p; mbarrier.try_wait.parity.acquire.cta.shared::cta.b64 p, [%1], %2, 0x989680; selp.b32 %0,1,0,p; }"
            : "=r"(done) : "r"(addr), "r"(parity) : "memory");
    } while (!done);
}

// Dummy kernel: aligns the ncu capture slot (4th launch is captured).
__global__ void dummy_kernel(int tag) {
    if (tag == 12345 && threadIdx.x == 0) g_dummy = tag;
}

// ---------------------------------------------------------------------------
// Fused 2-layer LSTM, one group per 8-CTA cluster, wave-staggered.
// Grid: 512 CTAs = 64 clusters. CTA rank owns hidden units [32r, 32r+32)
// -> 128 gate rows. 512 threads: row rl = tid>>2, quarter q = tid&3.
// 3 x 64KB buffers, 8 single-use mbarriers (all waits at parity 0):
//   mb0: A<-Wih0(b01)  mb1: B<-Wih0(b23)  mb2: C<-Whh0(b01)  mb3: B<-Whh0(b23)
//   mb4: A<-Wih1(b01)  mb5: C<-Wih1(b23)  mb6: B<-Whh1(b01)  mb7: A<-Whh1(b23)
// Wih1 + Whh1-lo stream during rec0. Layer-1 input captured into xs from
// the per-step h broadcast (no global round-trip).
// ---------------------------------------------------------------------------
#define SMEM_BYTES 215040

__global__ void __cluster_dims__(8, 1, 1) __launch_bounds__(512, 1)
lstm_fused2_kernel(const float* __restrict__ Wih0, const float* __restrict__ Whh0,
                   const float* __restrict__ bih0, const float* __restrict__ bhh0,
                   const float* __restrict__ Wih1, const float* __restrict__ Whh1,
                   const float* __restrict__ bih1, const float* __restrict__ bhh1,
                   const float* __restrict__ data, float* __restrict__ out)
{
    extern __shared__ __align__(16) char smem[];
    float* A      = (float*)(smem);
    float* B      = (float*)(smem + 65536);
    float* C      = (float*)(smem + 131072);
    float* xs     = (float*)(smem + 196608);   // 10KB swizzled input rows
    float* xgp    = (float*)(smem + 206848);   // 5KB [t][row]
    float* h_buf  = (float*)(smem + 211968);   // 2KB double buffer (swizzled)
    float* gate_s = (float*)(smem + 214016);   // 512B
    const unsigned int mb = smem_u32(smem + 214528);  // 8 single-use mbarriers

    const int g    = blockIdx.x >> 3;          // group = cluster id
    const int rank = blockIdx.x & 7;
    const int tid  = threadIdx.x;
    const int rl   = tid >> 2;                 // 0..127 local row
    const int q    = tid & 3;                  // column quarter
    const int gate = rl >> 5;
    const int ul   = rl & 31;
    const int grow = gate * 256 + rank * 32 + ul;
    const int qh   = q ^ (q << 1);
    const int au   = tid >> 3;                 // activation unit (tid<256)
    const int ar   = tid & 7;                  // activation target rank

    if (tid == 0) {
        #pragma unroll
        for (int i = 0; i < 8; i++) mbar_init(mb + i * 8, 1);
    }
    __syncthreads();

    // TMA issue helper: 2 x 32KB gate blocks into one 64KB buffer.
    auto issue2 = [&](unsigned int mbar, float* buf, const float* M, int b0, int b1) {
        mbar_expect(mbar, 65536);
        bulk_g2s(smem_u32(buf),         M + ((size_t)g * 1024 + b0 * 256 + rank * 32) * 256, 32768, mbar);
        bulk_g2s(smem_u32(buf) + 32768, M + ((size_t)g * 1024 + b1 * 256 + rank * 32) * 256, 32768, mbar);
    };

    if (tid == 0) {
        issue2(mb + 0,  A, Wih0, 0, 1);
        issue2(mb + 8,  B, Wih0, 2, 3);
        issue2(mb + 16, C, Whh0, 0, 1);   // Whh0-lo prefetched immediately
    }

    // xs = data[g] (swizzled); zero h(-1) buffer
    for (int e = tid; e < T_ * 256; e += 512) {
        int t = e >> 8, u = e & 255;
        xs[t * 256 + (u ^ ((u & 0xC0) >> 3))] = data[((size_t)t * G_ + g) * 256 + u];
    }
    if (tid < 256) h_buf[tid] = 0.0f;
    __syncthreads();   // xs fill + zeros complete before any consumption

    ulonglong2 wreg[16];

    // input projection: xgp[t][rl] = bias + dot(W[grow], xs[t])  (quarter+reduce)
    auto run_xg = [&](const float* lobuf, const float* hibuf,
                      const float* bihp, const float* bhhp) {
        const ulonglong2* wsrc = (const ulonglong2*)((rl < 64) ? (lobuf + rl * 256)
                                                               : (hibuf + (rl - 64) * 256));
        const ulonglong2* xs2 = (const ulonglong2*)xs;
        unsigned long long xa[T_];
        #pragma unroll
        for (int t = 0; t < T_; t++) xa[t] = 0ull;
        #pragma unroll 2
        for (int i = 0; i < 16; i++) {
            ulonglong2 w = wsrc[16 * q + (i ^ q)];
            const int xi = 16 * q + (i ^ qh);
            #pragma unroll
            for (int t = 0; t < T_; t++) {
                ulonglong2 x = xs2[t * 64 + xi];
                fma2(xa[t], w.x, x.x);
                fma2(xa[t], w.y, x.y);
            }
        }
        const float bias = (q == 0)
            ? bihp[(size_t)g * H4_ + grow] + bhhp[(size_t)g * H4_ + grow] : 0.0f;
        #pragma unroll
        for (int t = 0; t < T_; t++) {
            float s = unpack_sum(xa[t]);
            s += __shfl_xor_sync(0xffffffffu, s, 1);
            s += __shfl_xor_sync(0xffffffffu, s, 2);
            if (q == 0) xgp[t * 128 + rl] = s + bias;
        }
        __syncthreads();   // buffer reads done; xgp complete
    };

    auto load_wreg = [&](const float* lobuf, const float* hibuf) {
        const ulonglong2* src = (const ulonglong2*)((rl < 64) ? (lobuf + rl * 256)
                                                              : (hibuf + (rl - 64) * 256));
        #pragma unroll
        for (int i = 0; i < 16; i++) wreg[i] = src[16 * q + (i ^ q)];
        __syncthreads();   // buffer consumed -> reusable
    };

    const unsigned int hbase = smem_u32(h_buf);

    // 10-step recurrence. 256 threads compute activations (x8 redundant) so the
    // h broadcast is ONE remote store per thread instead of 8 from one warp.
    auto run_rec = [&](int layer) {
        float* hdst = g_h2 + (size_t)g * T_ * 256;
        float c_reg = 0.0f, h_last = 0.0f;
        int p = 0;
        for (int t = 0; t < T_; t++) {
            if (layer == 0 && t > 0 && tid < 256)
                xs[(t - 1) * 256 + tid] = h_buf[p * 256 + tid];   // capture h1 for xg1

            const ulonglong2* h2 = (const ulonglong2*)(h_buf + p * 256);
            unsigned long long a0 = 0ull, a1 = 0ull;
            #pragma unroll
            for (int i = 0; i < 16; i++) {
                ulonglong2 h = h2[16 * q + (i ^ qh)];
                fma2(a0, wreg[i].x, h.x);
                fma2(a1, wreg[i].y, h.y);
            }
            float s = unpack_sum(a0) + unpack_sum(a1);
            s += __shfl_xor_sync(0xffffffffu, s, 1);
            s += __shfl_xor_sync(0xffffffffu, s, 2);
            if (q == 0) gate_s[rl] = s + xgp[t * 128 + rl];
            __syncthreads();

            if (tid < 256) {
                float ig = gate_s[au];
                float fg = gate_s[32 + au];
                float gg = gate_s[64 + au];
                float og = gate_s[96 + au];
                c_reg = sigf(fg) * c_reg + sigf(ig) * fast_tanh(gg);
                float h = sigf(og) * fast_tanh(c_reg);
                h_last = h;
                if (layer && ar == 0) hdst[(size_t)t * 256 + rank * 32 + au] = h;
                const int gu = rank * 32 + au;
                const int phys = gu ^ ((gu & 0xC0) >> 3);
                st_cluster_f32(hbase + (unsigned)((1 - p) * 256 + phys) * 4u, (unsigned)ar, h);
            }
            CLUSTER_SYNC();   // h(t) visible cluster-wide; all reads of buf p retired
            p ^= 1;
        }
        if (layer == 0 && tid < 256)
            xs[(T_ - 1) * 256 + tid] = h_buf[p * 256 + tid];
        __syncthreads();

        if (tid < 256 && ar == 0) {
            out[OFF_HN + (size_t)g * 512 + layer * 256 + rank * 32 + au] = h_last;
            out[OFF_CN + (size_t)g * 512 + layer * 256 + rank * 32 + au] = c_reg;
        }
    };

    // ---------------- unit 0 (layer 0) ----------------
    mbar_wait(rl < 64 ? mb + 0 : mb + 8, 0);          // Wih0 halves
    run_xg(A, B, bih0, bhh0);
    if (tid == 0) issue2(mb + 24, B, Whh0, 2, 3);     // B free after xg0
    mbar_wait(rl < 64 ? mb + 16 : mb + 24, 0);        // Whh0 lo(C) / hi(B)
    load_wreg(C, B);
    if (tid == 0) {                                   // stream unit-1 weights during rec0
        issue2(mb + 32, A, Wih1, 0, 1);
        issue2(mb + 40, C, Wih1, 2, 3);
        issue2(mb + 48, B, Whh1, 0, 1);
    }
    CLUSTER_SYNC();                                   // zeros visible before DSMEM traffic
    run_rec(0);

    // ---------------- unit 1 (layer 1) ----------------
    if (tid < 256) h_buf[tid] = 0.0f;                 // re-zero h(-1) (local only)
    __syncthreads();
    mbar_wait(rl < 64 ? mb + 32 : mb + 40, 0);        // Wih1 halves (A / C)
    run_xg(A, C, bih1, bhh1);
    if (tid == 0) issue2(mb + 56, A, Whh1, 2, 3);     // A free after xg1
    mbar_wait(rl < 64 ? mb + 48 : mb + 56, 0);        // Whh1 lo(B) / hi(A)
    load_wreg(B, A);
    CLUSTER_SYNC();                                   // all CTAs fully past rec0
    run_rec(1);

    CLUSTER_SYNC();   // no CTA exits while peers may still target its SMEM
}

// ---------------------------------------------------------------------------
// Fused tail: per-group Wlin -> fc (SMEM) -> lin1/beta/gamma.
// Grid: 64 blocks (one per group) x 256 threads.
// ---------------------------------------------------------------------------
__global__ void __launch_bounds__(256)
tail_kernel(const float* __restrict__ Wlin, const float* __restrict__ blin,
            const float* __restrict__ W1, const float* __restrict__ b1,
            const float* __restrict__ W2, const float* __restrict__ b2,
            const float* __restrict__ Wd, const float* __restrict__ bd,
            float* __restrict__ out)
{
    __shared__ __align__(16) float hs [T_ * 256];
    __shared__ __align__(16) float fcs[T_ * 256];
    __shared__ float red[T_ * 8];

    const int g = blockIdx.x;
    const int j = threadIdx.x;
    const int lane = j & 31, warp = j >> 5;

    {
        const float4* hp4 = (const float4*)(g_h2 + (size_t)g * T_ * 256);
        float4* hw = (float4*)hs;
        for (int e = j; e < 640; e += 256) hw[e] = hp4[e];
    }
    __syncthreads();

    float acc[T_];
    #pragma unroll
    for (int t = 0; t < T_; t++) acc[t] = 0.0f;
    {
        const float4* wl  = (const float4*)(Wlin + ((size_t)g * 256 + j) * 256);
        const float4* hs4 = (const float4*)hs;
        #pragma unroll 4
        for (int i4 = 0; i4 < 64; i4++) {
            float4 w = wl[i4];
            #pragma unroll
            for (int t = 0; t < T_; t++) {
                float4 f = hs4[t * 64 + i4];
                acc[t] += w.x * f.x + w.y * f.y + w.z * f.z + w.w * f.w;
            }
        }
    }
    const float bl = blin[(size_t)g * 256 + j];
    #pragma unroll
    for (int t = 0; t < T_; t++) fcs[t * 256 + j] = acc[t] + bl;
    __syncthreads();

    float a1[T_], a2[T_];
    const float b1j = b1[j], b2j = b2[j];
    #pragma unroll
    for (int t = 0; t < T_; t++) { a1[t] = b1j; a2[t] = b2j; }
    {
        const float4* w1r = (const float4*)(W1 + (size_t)j * 256);
        const float4* w2r = (const float4*)(W2 + (size_t)j * 256);
        const float4* f4  = (const float4*)fcs;
        #pragma unroll 4
        for (int i4 = 0; i4 < 64; i4++) {
            float4 w1 = w1r[i4];
            float4 w2 = w2r[i4];
            #pragma unroll
            for (int t = 0; t < T_; t++) {
                float4 f = f4[t * 64 + i4];
                a1[t] += w1.x * f.x + w1.y * f.y + w1.z * f.z + w1.w * f.w;
                a2[t] += w2.x * f.x + w2.y * f.y + w2.z * f.z + w2.w * f.w;
            }
        }
    }
    const float wd = Wd[j];
    #pragma unroll
    for (int t = 0; t < T_; t++) {
        const size_t idx = ((size_t)g * T_ + t) * 256 + j;
        g_lin1[idx] = a1[t];
        float x = a2[t];
        out[OFF_BETA + idx] = (x > 20.0f) ? x : log1pf(__expf(x));
        float s = a1[t] * wd;
        #pragma unroll
        for (int o = 16; o > 0; o >>= 1) s += __shfl_xor_sync(0xffffffffu, s, o);
        if (lane == 0) red[t * 8 + warp] = s;
    }
    __syncthreads();
    if (j < T_) {
        float s = 0.0f;
        #pragma unroll
        for (int w = 0; w < 8; w++) s += red[j * 8 + w];
        out[OFF_GAMMA + (size_t)g * T_ + j] = s + bd[0];
    }
}

// ---------------------------------------------------------------------------
// Softmax over groups. Grid: (10, 4) x 64 threads; thread per (t, j).
// ---------------------------------------------------------------------------
__global__ void softmax_kernel(float* __restrict__ out)
{
    const int t = blockIdx.x;
    const int j = blockIdx.y * 64 + threadIdx.x;

    float v[G_];
    float m = -1e30f;
    #pragma unroll
    for (int g = 0; g < G_; g++) {
        v[g] = g_lin1[((size_t)g * T_ + t) * 256 + j];
        m = fmaxf(m, v[g]);
    }
    float s = 0.0f;
    #pragma unroll
    for (int g = 0; g < G_; g++) { v[g] = __expf(v[g] - m); s += v[g]; }
    const float inv = __fdividef(1.0f, s);
    #pragma unroll
    for (int g = 0; g < G_; g++)
        out[OFF_DELTA + ((size_t)g * T_ + t) * 256 + j] = v[g] * inv;
}

// ---------------------------------------------------------------------------
extern "C" void kernel_launch(void* const* d_in, const int* in_sizes, int n_in,
                              void* d_out, int out_size)
{
    const float* data = (const float*)d_in[0];
    const float* Wih0 = (const float*)d_in[1];
    const float* Whh0 = (const float*)d_in[2];
    const float* bih0 = (const float*)d_in[3];
    const float* bhh0 = (const float*)d_in[4];
    const float* Wih1 = (const float*)d_in[5];
    const float* Whh1 = (const float*)d_in[6];
    const float* bih1 = (const float*)d_in[7];
    const float* bhh1 = (const float*)d_in[8];
    const float* Wlin = (const float*)d_in[9];
    const float* blin = (const float*)d_in[10];
    const float* W1   = (const float*)d_in[11];
    const float* b1   = (const float*)d_in[12];
    const float* W2   = (const float*)d_in[13];
    const float* b2   = (const float*)d_in[14];
    const float* Wd   = (const float*)d_in[15];
    const float* bd   = (const float*)d_in[16];
    float* out = (float*)d_out;

    cudaFuncSetAttribute(lstm_fused2_kernel,
                         cudaFuncAttributeMaxDynamicSharedMemorySize, SMEM_BYTES);

    // 3 dummies: the 4th launch is the one ncu captures -> lstm_fused2_kernel.
    dummy_kernel<<<1, 32>>>(0);
    dummy_kernel<<<1, 32>>>(1);
    dummy_kernel<<<1, 32>>>(2);

    lstm_fused2_kernel<<<G_ * 8, 512, SMEM_BYTES>>>(Wih0, Whh0, bih0, bhh0,
                                                    Wih1, Whh1, bih1, bhh1, data, out);
    tail_kernel<<<64, 256>>>(Wlin, blin, W1, b1, W2, b2, Wd, bd, out);
    softmax_kernel<<<dim3(10, 4), 64>>>(out);
}

// round 9
// speedup vs baseline: 2.0958x; 1.0184x over previous
#include <cuda_runtime.h>
#include <cuda_bf16.h>
#include <math.h>
#include <stdint.h>

#define G_   64
#define T_   10
#define H_   256
#define H4_  1024

// Output offsets (tuple flattened: gamma, beta, delta, hN, cN)
#define OFF_GAMMA 0
#define OFF_BETA  640
#define OFF_DELTA 164480
#define OFF_HN    328320
#define OFF_CN    361088

// Scratch
__device__ float g_h2  [G_ * T_ * H_];
__device__ float g_lin1[G_ * T_ * H_];
__device__ int   g_dummy;

__device__ __forceinline__ float fast_tanh(float x) {
    float r;
    asm("tanh.approx.f32 %0, %1;" : "=f"(r) : "f"(x));
    return r;
}
__device__ __forceinline__ float sigf(float x) {
    return __fdividef(1.0f, 1.0f + __expf(-x));
}
__device__ __forceinline__ void fma2(unsigned long long& acc, unsigned long long a, unsigned long long b) {
    asm("fma.rn.f32x2 %0, %1, %2, %0;" : "+l"(acc) : "l"(a), "l"(b));
}
__device__ __forceinline__ float unpack_sum(unsigned long long v) {
    unsigned int lo, hi;
    asm("mov.b64 {%0, %1}, %2;" : "=r"(lo), "=r"(hi) : "l"(v));
    return __uint_as_float(lo) + __uint_as_float(hi);
}
__device__ __forceinline__ unsigned int smem_u32(const void* p) {
    unsigned int a;
    asm("{ .reg .u64 t; cvta.to.shared.u64 t, %1; cvt.u32.u64 %0, t; }" : "=r"(a) : "l"(p));
    return a;
}
// Async store to CTA `rank`'s SMEM with 4-byte tx completion on its mbarrier.
__device__ __forceinline__ void st_async_f32(unsigned int saddr, unsigned int smbar,
                                             unsigned int rank, float v) {
    asm volatile(
        "{ .reg .b32 ra, rb;\n"
        "  mapa.shared::cluster.u32 ra, %0, %2;\n"
        "  mapa.shared::cluster.u32 rb, %1, %2;\n"
        "  st.async.shared::cluster.mbarrier::complete_tx::bytes.b32 [ra], %3, [rb]; }"
        :: "r"(saddr), "r"(smbar), "r"(rank), "f"(v) : "memory");
}
// Cluster-scope acquire wait (orders remote st.async data on phase flip).
__device__ __forceinline__ void mbar_wait_cl(unsigned int addr, unsigned int parity) {
    unsigned int done;
    do {
        asm volatile(
            "{ .reg .pred p; mbarrier.try_wait.parity.acquire.cluster.shared::cta.b64 p, [%1], %2, 0x989680; selp.b32 %0,1,0,p; }"
            : "=r"(done) : "r"(addr), "r"(parity) : "memory");
    } while (!done);
}
#define CLUSTER_SYNC() do { \
    asm volatile("barrier.cluster.arrive.aligned;" ::: "memory"); \
    asm volatile("barrier.cluster.wait.aligned;"   ::: "memory"); } while (0)

__device__ __forceinline__ void bulk_g2s(unsigned int dst, const void* src,
                                         unsigned int bytes, unsigned int mbar) {
    asm volatile(
        "cp.async.bulk.shared::cluster.global.mbarrier::complete_tx::bytes [%0], [%1], %2, [%3];"
        :: "r"(dst), "l"(src), "r"(bytes), "r"(mbar) : "memory");
}
__device__ __forceinline__ void mbar_init(unsigned int addr, unsigned int cnt) {
    asm volatile("mbarrier.init.shared.b64 [%0], %1;" :: "r"(addr), "r"(cnt) : "memory");
}
__device__ __forceinline__ void mbar_expect(unsigned int addr, unsigned int bytes) {
    asm volatile("mbarrier.arrive.expect_tx.shared.b64 _, [%0], %1;" :: "r"(addr), "r"(bytes) : "memory");
}
__device__ __forceinline__ void mbar_wait(unsigned int addr, unsigned int parity) {
    unsigned int done;
    do {
        asm volatile(
            "{ .reg .pred p; mbarrier.try_wait.parity.acquire.cta.shared::cta.b64 p, [%1], %2, 0x989680; selp.b32 %0,1,0,p; }"
            : "=r"(done) : "r"(addr), "r"(parity) : "memory");
    } while (!done);
}

// Dummy kernel: aligns the ncu capture slot (4th launch is captured).
__global__ void dummy_kernel(int tag) {
    if (tag == 12345 && threadIdx.x == 0) g_dummy = tag;
}

// ---------------------------------------------------------------------------
// Fused 2-layer LSTM, one group per 8-CTA cluster, wave-staggered.
// Grid: 512 CTAs = 64 clusters. 512 threads: row rl = tid>>2, quarter q = tid&3.
// Weights TMA-streamed into 3x64KB buffers (8 single-use mbarriers, parity 0).
// Recurrence sync: st.async h-broadcast with tx-count full[2] mbarriers
// (1024 bytes = 32 values x 8 peers per phase). No empty barrier: a peer's
// step-t delivery is gated on MY step-(t-1) arrival, which I issue only after
// finishing all reads of the buffer that step-t overwrites.
// ---------------------------------------------------------------------------
#define SMEM_BYTES 215040

__global__ void __cluster_dims__(8, 1, 1) __launch_bounds__(512, 1)
lstm_fused2_kernel(const float* __restrict__ Wih0, const float* __restrict__ Whh0,
                   const float* __restrict__ bih0, const float* __restrict__ bhh0,
                   const float* __restrict__ Wih1, const float* __restrict__ Whh1,
                   const float* __restrict__ bih1, const float* __restrict__ bhh1,
                   const float* __restrict__ data, float* __restrict__ out)
{
    extern __shared__ __align__(16) char smem[];
    float* A      = (float*)(smem);
    float* B      = (float*)(smem + 65536);
    float* C      = (float*)(smem + 131072);
    float* xs     = (float*)(smem + 196608);   // 10KB swizzled input rows
    float* xgp    = (float*)(smem + 206848);   // 5KB [t][row]
    float* h_buf  = (float*)(smem + 211968);   // 2KB double buffer (swizzled)
    float* gate_s = (float*)(smem + 214016);   // 512B
    const unsigned int mb  = smem_u32(smem + 214528);  // 8 TMA mbarriers
    const unsigned int mbF = smem_u32(smem + 214592);  // full0, full1 (tx-count)

    const int g    = blockIdx.x >> 3;          // group = cluster id
    const int rank = blockIdx.x & 7;
    const int tid  = threadIdx.x;
    const int rl   = tid >> 2;                 // 0..127 local row
    const int q    = tid & 3;                  // column quarter
    const int gate = rl >> 5;
    const int ul   = rl & 31;
    const int grow = gate * 256 + rank * 32 + ul;
    const int qh   = q ^ (q << 1);
    const int au   = tid >> 3;                 // activation unit (tid<256)
    const int ar   = tid & 7;                  // activation target rank

    if (tid == 0) {
        #pragma unroll
        for (int i = 0; i < 8; i++) mbar_init(mb + i * 8, 1);
        mbar_init(mbF + 0, 1); mbar_init(mbF + 8, 1);
        mbar_expect(mbF + 0, 1024);   // arm phase 0 (both buffers)
        mbar_expect(mbF + 8, 1024);
    }
    __syncthreads();

    auto issue2 = [&](unsigned int mbar, float* buf, const float* M, int b0, int b1) {
        mbar_expect(mbar, 65536);
        bulk_g2s(smem_u32(buf),         M + ((size_t)g * 1024 + b0 * 256 + rank * 32) * 256, 32768, mbar);
        bulk_g2s(smem_u32(buf) + 32768, M + ((size_t)g * 1024 + b1 * 256 + rank * 32) * 256, 32768, mbar);
    };

    if (tid == 0) {
        issue2(mb + 0,  A, Wih0, 0, 1);
        issue2(mb + 8,  B, Wih0, 2, 3);
        issue2(mb + 16, C, Whh0, 0, 1);
    }

    for (int e = tid; e < T_ * 256; e += 512) {
        int t = e >> 8, u = e & 255;
        xs[t * 256 + (u ^ ((u & 0xC0) >> 3))] = data[((size_t)t * G_ + g) * 256 + u];
    }
    if (tid < 256) h_buf[tid] = 0.0f;
    __syncthreads();   // xs fill + zeros complete

    ulonglong2 wreg[16];

    auto run_xg = [&](const float* lobuf, const float* hibuf,
                      const float* bihp, const float* bhhp) {
        const ulonglong2* wsrc = (const ulonglong2*)((rl < 64) ? (lobuf + rl * 256)
                                                               : (hibuf + (rl - 64) * 256));
        const ulonglong2* xs2 = (const ulonglong2*)xs;
        unsigned long long xa[T_];
        #pragma unroll
        for (int t = 0; t < T_; t++) xa[t] = 0ull;
        #pragma unroll 2
        for (int i = 0; i < 16; i++) {
            ulonglong2 w = wsrc[16 * q + (i ^ q)];
            const int xi = 16 * q + (i ^ qh);
            #pragma unroll
            for (int t = 0; t < T_; t++) {
                ulonglong2 x = xs2[t * 64 + xi];
                fma2(xa[t], w.x, x.x);
                fma2(xa[t], w.y, x.y);
            }
        }
        const float bias = (q == 0)
            ? bihp[(size_t)g * H4_ + grow] + bhhp[(size_t)g * H4_ + grow] : 0.0f;
        #pragma unroll
        for (int t = 0; t < T_; t++) {
            float s = unpack_sum(xa[t]);
            s += __shfl_xor_sync(0xffffffffu, s, 1);
            s += __shfl_xor_sync(0xffffffffu, s, 2);
            if (q == 0) xgp[t * 128 + rl] = s + bias;
        }
        __syncthreads();
    };

    auto load_wreg = [&](const float* lobuf, const float* hibuf) {
        const ulonglong2* src = (const ulonglong2*)((rl < 64) ? (lobuf + rl * 256)
                                                              : (hibuf + (rl - 64) * 256));
        #pragma unroll
        for (int i = 0; i < 16; i++) wreg[i] = src[16 * q + (i ^ q)];
        __syncthreads();
    };

    const unsigned int hbase = smem_u32(h_buf);
    unsigned int f0 = 0, f1 = 0;   // full-barrier parities (persist across units)

    auto run_rec = [&](int layer) {
        float* hdst = g_h2 + (size_t)g * T_ * 256;
        float c_reg = 0.0f, h_last = 0.0f;
        for (int t = 0; t < T_; t++) {
            const int br = t & 1;
            if (t > 0) {   // wait h(t-1) delivered into buf br; re-arm after flip
                if (br) { mbar_wait_cl(mbF + 8, f1); f1 ^= 1; if (tid == 0) mbar_expect(mbF + 8, 1024); }
                else    { mbar_wait_cl(mbF + 0, f0); f0 ^= 1; if (tid == 0) mbar_expect(mbF + 0, 1024); }
            }
            if (layer == 0 && t > 0 && tid < 256)
                xs[(t - 1) * 256 + tid] = h_buf[br * 256 + tid];   // capture h1 for xg1

            const ulonglong2* h2 = (const ulonglong2*)(h_buf + br * 256);
            unsigned long long a0 = 0ull, a1 = 0ull;
            #pragma unroll
            for (int i = 0; i < 16; i++) {
                ulonglong2 h = h2[16 * q + (i ^ qh)];
                fma2(a0, wreg[i].x, h.x);
                fma2(a1, wreg[i].y, h.y);
            }
            float s = unpack_sum(a0) + unpack_sum(a1);
            s += __shfl_xor_sync(0xffffffffu, s, 1);
            s += __shfl_xor_sync(0xffffffffu, s, 2);
            if (q == 0) gate_s[rl] = s + xgp[t * 128 + rl];
            __syncthreads();   // gate_s ready; all reads of buf br retired

            if (tid < 256) {
                float ig = gate_s[au];
                float fg = gate_s[32 + au];
                float gg = gate_s[64 + au];
                float og = gate_s[96 + au];
                c_reg = sigf(fg) * c_reg + sigf(ig) * fast_tanh(gg);
                float h = sigf(og) * fast_tanh(c_reg);
                h_last = h;
                if (layer && ar == 0) hdst[(size_t)t * 256 + rank * 32 + au] = h;
                const int bw = br ^ 1;
                const int gu = rank * 32 + au;
                const int phys = gu ^ ((gu & 0xC0) >> 3);
                st_async_f32(hbase + (unsigned)(bw * 256 + phys) * 4u,
                             mbF + (unsigned)bw * 8u, (unsigned)ar, h);
            }
            // no barrier: next iteration's mbarrier wait provides all ordering
        }
        // drain h(9) (delivered into buf0), re-arm for next unit
        mbar_wait_cl(mbF + 0, f0); f0 ^= 1; if (tid == 0) mbar_expect(mbF + 0, 1024);
        if (layer == 0 && tid < 256)
            xs[(T_ - 1) * 256 + tid] = h_buf[tid];
        __syncthreads();

        if (tid < 256 && ar == 0) {
            out[OFF_HN + (size_t)g * 512 + layer * 256 + rank * 32 + au] = h_last;
            out[OFF_CN + (size_t)g * 512 + layer * 256 + rank * 32 + au] = c_reg;
        }
    };

    // ---------------- unit 0 (layer 0) ----------------
    mbar_wait(rl < 64 ? mb + 0 : mb + 8, 0);          // Wih0 halves
    run_xg(A, B, bih0, bhh0);
    if (tid == 0) issue2(mb + 24, B, Whh0, 2, 3);     // B free after xg0
    mbar_wait(rl < 64 ? mb + 16 : mb + 24, 0);        // Whh0 lo(C) / hi(B)
    load_wreg(C, B);
    if (tid == 0) {                                   // stream unit-1 weights during rec0
        issue2(mb + 32, A, Wih1, 0, 1);
        issue2(mb + 40, C, Wih1, 2, 3);
        issue2(mb + 48, B, Whh1, 0, 1);
    }
    CLUSTER_SYNC();   // mbarrier inits + armings + zeros visible before any st.async
    run_rec(0);

    // ---------------- unit 1 (layer 1) ----------------
    if (tid < 256) h_buf[tid] = 0.0f;                 // re-zero h(-1) (local only)
    __syncthreads();
    mbar_wait(rl < 64 ? mb + 32 : mb + 40, 0);        // Wih1 halves (A / C)
    run_xg(A, C, bih1, bhh1);
    if (tid == 0) issue2(mb + 56, A, Whh1, 2, 3);     // A free after xg1
    mbar_wait(rl < 64 ? mb + 48 : mb + 56, 0);        // Whh1 lo(B) / hi(A)
    load_wreg(B, A);
    CLUSTER_SYNC();                                   // all CTAs fully past rec0
    run_rec(1);

    CLUSTER_SYNC();   // no CTA exits while peers may still target its SMEM
}

// ---------------------------------------------------------------------------
// Fused tail: per-group Wlin -> fc (SMEM) -> lin1/beta/gamma.
// Grid: 64 blocks x 512 threads (t-split: th = tid>>8 covers 5 timesteps).
// ---------------------------------------------------------------------------
__global__ void __launch_bounds__(512)
tail_kernel(const float* __restrict__ Wlin, const float* __restrict__ blin,
            const float* __restrict__ W1, const float* __restrict__ b1,
            const float* __restrict__ W2, const float* __restrict__ b2,
            const float* __restrict__ Wd, const float* __restrict__ bd,
            float* __restrict__ out)
{
    __shared__ __align__(16) float hs [T_ * 256];
    __shared__ __align__(16) float fcs[T_ * 256];
    __shared__ float red[T_ * 8];

    const int g   = blockIdx.x;
    const int tid = threadIdx.x;
    const int j   = tid & 255;
    const int th  = tid >> 8;         // 0/1 -> t in [5*th, 5*th+5)
    const int t0  = th * 5;
    const int lane = tid & 31, w8 = (tid >> 5) & 7;

    {
        const float4* hp4 = (const float4*)(g_h2 + (size_t)g * T_ * 256);
        float4* hw = (float4*)hs;
        for (int e = tid; e < 640; e += 512) hw[e] = hp4[e];
    }
    __syncthreads();

    float acc[5];
    #pragma unroll
    for (int tt = 0; tt < 5; tt++) acc[tt] = 0.0f;
    {
        const float4* wl  = (const float4*)(Wlin + ((size_t)g * 256 + j) * 256);
        const float4* hs4 = (const float4*)hs;
        #pragma unroll 4
        for (int i4 = 0; i4 < 64; i4++) {
            float4 w = wl[i4];
            #pragma unroll
            for (int tt = 0; tt < 5; tt++) {
                float4 f = hs4[(t0 + tt) * 64 + i4];
                acc[tt] += w.x * f.x + w.y * f.y + w.z * f.z + w.w * f.w;
            }
        }
    }
    const float bl = blin[(size_t)g * 256 + j];
    #pragma unroll
    for (int tt = 0; tt < 5; tt++) fcs[(t0 + tt) * 256 + j] = acc[tt] + bl;
    __syncthreads();

    float a1[5], a2[5];
    const float b1j = b1[j], b2j = b2[j];
    #pragma unroll
    for (int tt = 0; tt < 5; tt++) { a1[tt] = b1j; a2[tt] = b2j; }
    {
        const float4* w1r = (const float4*)(W1 + (size_t)j * 256);
        const float4* w2r = (const float4*)(W2 + (size_t)j * 256);
        const float4* f4  = (const float4*)fcs;
        #pragma unroll 4
        for (int i4 = 0; i4 < 64; i4++) {
            float4 w1 = w1r[i4];
            float4 w2 = w2r[i4];
            #pragma unroll
            for (int tt = 0; tt < 5; tt++) {
                float4 f = f4[(t0 + tt) * 64 + i4];
                a1[tt] += w1.x * f.x + w1.y * f.y + w1.z * f.z + w1.w * f.w;
                a2[tt] += w2.x * f.x + w2.y * f.y + w2.z * f.z + w2.w * f.w;
            }
        }
    }
    const float wd = Wd[j];
    #pragma unroll
    for (int tt = 0; tt < 5; tt++) {
        const int t = t0 + tt;
        const size_t idx = ((size_t)g * T_ + t) * 256 + j;
        g_lin1[idx] = a1[tt];
        float x = a2[tt];
        out[OFF_BETA + idx] = (x > 20.0f) ? x : log1pf(__expf(x));
        float s = a1[tt] * wd;
        #pragma unroll
        for (int o = 16; o > 0; o >>= 1) s += __shfl_xor_sync(0xffffffffu, s, o);
        if (lane == 0) red[t * 8 + w8] = s;
    }
    __syncthreads();
    if (tid < T_) {
        float s = 0.0f;
        #pragma unroll
        for (int w = 0; w < 8; w++) s += red[tid * 8 + w];
        out[OFF_GAMMA + (size_t)g * T_ + tid] = s + bd[0];
    }
}

// ---------------------------------------------------------------------------
// Softmax over groups. Grid: (10, 4) x 64 threads; thread per (t, j).
// ---------------------------------------------------------------------------
__global__ void softmax_kernel(float* __restrict__ out)
{
    const int t = blockIdx.x;
    const int j = blockIdx.y * 64 + threadIdx.x;

    float v[G_];
    float m = -1e30f;
    #pragma unroll
    for (int g = 0; g < G_; g++) {
        v[g] = g_lin1[((size_t)g * T_ + t) * 256 + j];
        m = fmaxf(m, v[g]);
    }
    float s = 0.0f;
    #pragma unroll
    for (int g = 0; g < G_; g++) { v[g] = __expf(v[g] - m); s += v[g]; }
    const float inv = __fdividef(1.0f, s);
    #pragma unroll
    for (int g = 0; g < G_; g++)
        out[OFF_DELTA + ((size_t)g * T_ + t) * 256 + j] = v[g] * inv;
}

// ---------------------------------------------------------------------------
extern "C" void kernel_launch(void* const* d_in, const int* in_sizes, int n_in,
                              void* d_out, int out_size)
{
    const float* data = (const float*)d_in[0];
    const float* Wih0 = (const float*)d_in[1];
    const float* Whh0 = (const float*)d_in[2];
    const float* bih0 = (const float*)d_in[3];
    const float* bhh0 = (const float*)d_in[4];
    const float* Wih1 = (const float*)d_in[5];
    const float* Whh1 = (const float*)d_in[6];
    const float* bih1 = (const float*)d_in[7];
    const float* bhh1 = (const float*)d_in[8];
    const float* Wlin = (const float*)d_in[9];
    const float* blin = (const float*)d_in[10];
    const float* W1   = (const float*)d_in[11];
    const float* b1   = (const float*)d_in[12];
    const float* W2   = (const float*)d_in[13];
    const float* b2   = (const float*)d_in[14];
    const float* Wd   = (const float*)d_in[15];
    const float* bd   = (const float*)d_in[16];
    float* out = (float*)d_out;

    cudaFuncSetAttribute(lstm_fused2_kernel,
                         cudaFuncAttributeMaxDynamicSharedMemorySize, SMEM_BYTES);

    // 3 dummies: the 4th launch is the one ncu captures -> lstm_fused2_kernel.
    dummy_kernel<<<1, 32>>>(0);
    dummy_kernel<<<1, 32>>>(1);
    dummy_kernel<<<1, 32>>>(2);

    lstm_fused2_kernel<<<G_ * 8, 512, SMEM_BYTES>>>(Wih0, Whh0, bih0, bhh0,
                                                    Wih1, Whh1, bih1, bhh1, data, out);
    tail_kernel<<<64, 512>>>(Wlin, blin, W1, b1, W2, b2, Wd, bd, out);
    softmax_kernel<<<dim3(10, 4), 64>>>(out);
}